// round 1
// baseline (speedup 1.0000x reference)
#include <cuda_runtime.h>
#include <math.h>

#define NEG_SLOPE 0.01f
#define MAXN 100000
#define HID 64
#define INC 128
#define OUTC 5

// ---------------- scratch (device globals; no allocation allowed) ----------------
__device__ int   g_w8;                       // 1 if indices are int64, 0 if int32
__device__ float g_deg [MAXN];
__device__ float g_dinv[MAXN];
__device__ __align__(16) float g_h   [(size_t)MAXN * HID];   // layer1 pre-agg  (x@W0)
__device__ __align__(16) float g_agg [(size_t)MAXN * HID];   // layer1 aggregate
__device__ __align__(16) float g_h1  [(size_t)MAXN * HID];   // layer2 pre-agg  (act@W1)
__device__ __align__(16) float g_agg1[(size_t)MAXN * HID];   // layer2 aggregate

// ---------------- helpers ----------------
__device__ __forceinline__ int ldidx(const void* p, long long i, int w8) {
    return w8 ? (int)__ldg((const long long*)p + i) : __ldg((const int*)p + i);
}

__device__ __forceinline__ void red4(float* p, float4 v) {
    asm volatile("red.global.add.v4.f32 [%0], {%1,%2,%3,%4};"
                 :: "l"(p), "f"(v.x), "f"(v.y), "f"(v.z), "f"(v.w) : "memory");
}

__device__ __forceinline__ float leaky(float v) { return v > 0.f ? v : NEG_SLOPE * v; }

// ---------------- dtype detection ----------------
// int64 little-endian with values < 2^31: every odd int32 position is 0.
__global__ void detect_kernel(const unsigned int* p) {
    __shared__ int nz;
    if (threadIdx.x == 0) nz = 0;
    __syncthreads();
    if (p[2 * threadIdx.x + 1] != 0u) atomicExch(&nz, 1);
    __syncthreads();
    if (threadIdx.x == 0) g_w8 = (nz == 0) ? 1 : 0;
}

// ---------------- degree / normalization ----------------
__global__ void init_deg_kernel(int n) {
    int i = blockIdx.x * blockDim.x + threadIdx.x;
    if (i < n) g_deg[i] = 1.0f;  // self-loop
}

__global__ void count_deg_kernel(const void* ei, int e32) {
    int w8 = g_w8;
    long long E = w8 ? (e32 >> 1) : e32;
    long long e = (long long)blockIdx.x * blockDim.x + threadIdx.x;
    if (e >= E) return;
    int d = ldidx(ei, E + e, w8);
    atomicAdd(&g_deg[d], 1.0f);
}

__global__ void dinv_kernel(int n) {
    int i = blockIdx.x * blockDim.x + threadIdx.x;
    if (i < n) g_dinv[i] = rsqrtf(g_deg[i]);
}

// ---------------- fused GEMM (+ optional activation on input, self-loop agg init) ----------------
// LAYER==1: H = Xext @ W            ; out g_h,  g_agg  = dinv^2 * H
// LAYER==2: A = leaky(g_agg + bias) ; H = A @ W ; out g_h1, g_agg1 = dinv^2 * H
template<int K, int LAYER>
__global__ void gemm_kernel(const float* __restrict__ Xext,
                            const float* __restrict__ W,
                            const float* __restrict__ bias,
                            int n)
{
    const int CK = 32;
    __shared__ float Xs[64][CK + 1];
    __shared__ __align__(16) float Ws[CK][64];

    int tid = threadIdx.x;
    int tx = tid & 15;          // 16 col-groups of 4
    int ty = tid >> 4;          // 16 row-groups of 4
    int rb = blockIdx.x * 64;

    float acc[4][4] = {};

    for (int kc = 0; kc < K; kc += CK) {
        // stage X chunk (with fused bias+leaky for layer 2)
        for (int i = tid; i < 64 * CK; i += 256) {
            int r = i >> 5, c = i & 31;
            int row = rb + r;
            float v = 0.f;
            if (row < n) {
                if (LAYER == 1) {
                    v = Xext[(long long)row * K + kc + c];
                } else {
                    v = g_agg[(long long)row * K + kc + c] + bias[kc + c];
                    v = leaky(v);
                }
            }
            Xs[r][c] = v;
        }
        // stage W chunk
        for (int i = tid; i < CK * 64; i += 256) {
            int k = i >> 6, c = i & 63;
            Ws[k][c] = W[(long long)(kc + k) * 64 + c];
        }
        __syncthreads();

        #pragma unroll
        for (int kk = 0; kk < CK; kk++) {
            float4 wv = *(const float4*)&Ws[kk][tx * 4];
            #pragma unroll
            for (int i = 0; i < 4; i++) {
                float xv = Xs[ty * 4 + i][kk];
                acc[i][0] += xv * wv.x;
                acc[i][1] += xv * wv.y;
                acc[i][2] += xv * wv.z;
                acc[i][3] += xv * wv.w;
            }
        }
        __syncthreads();
    }

    float* H   = (LAYER == 1) ? g_h   : g_h1;
    float* AGG = (LAYER == 1) ? g_agg : g_agg1;
    #pragma unroll
    for (int i = 0; i < 4; i++) {
        int row = rb + ty * 4 + i;
        if (row >= n) break;
        float di = g_dinv[row];
        float d2 = di * di;
        float4 hv = make_float4(acc[i][0], acc[i][1], acc[i][2], acc[i][3]);
        *(float4*)&H[(long long)row * 64 + tx * 4] = hv;
        float4 av = make_float4(hv.x * d2, hv.y * d2, hv.z * d2, hv.w * d2);
        *(float4*)&AGG[(long long)row * 64 + tx * 4] = av;
    }
}

// ---------------- edge scatter: AGG[dst] += H[src] * dinv[src]*dinv[dst] ----------------
// 16 threads per edge, each handles one float4 (red.global.add.v4.f32).
template<int LAYER>
__global__ void scatter_kernel(const void* ei, int e32)
{
    int w8 = g_w8;
    long long E = w8 ? (e32 >> 1) : e32;
    long long gid = (long long)blockIdx.x * blockDim.x + threadIdx.x;
    long long e = gid >> 4;
    int part = (int)(gid & 15);
    if (e >= E) return;

    int s = ldidx(ei, e, w8);
    int d = ldidx(ei, E + e, w8);
    float c = __ldg(&g_dinv[s]) * __ldg(&g_dinv[d]);

    const float* H = (LAYER == 1) ? g_h   : g_h1;
    float*     AGG = (LAYER == 1) ? g_agg : g_agg1;

    float4 hv = *(const float4*)(H + (long long)s * 64 + part * 4);
    float4 m = make_float4(hv.x * c, hv.y * c, hv.z * c, hv.w * c);
    red4(AGG + (long long)d * 64 + part * 4, m);
}

// ---------------- final: select rows, activation, tiny MLP + sigmoid ----------------
// one warp per selected row
__global__ void final_kernel(const void* idxp, int nsel,
                             const float* __restrict__ b1,
                             const float* __restrict__ Wm,
                             const float* __restrict__ bm,
                             float* __restrict__ out_hsel,
                             float* __restrict__ out_prob)
{
    int w8 = g_w8;
    int warp = (blockIdx.x * blockDim.x + threadIdx.x) >> 5;
    int lane = threadIdx.x & 31;
    if (warp >= nsel) return;

    int v = ldidx(idxp, warp, w8);
    float a0 = leaky(g_agg1[(long long)v * 64 + lane]      + __ldg(&b1[lane]));
    float a1 = leaky(g_agg1[(long long)v * 64 + lane + 32] + __ldg(&b1[lane + 32]));
    out_hsel[(long long)warp * 64 + lane]      = a0;
    out_hsel[(long long)warp * 64 + lane + 32] = a1;

    #pragma unroll
    for (int j = 0; j < OUTC; j++) {
        float p = a0 * __ldg(&Wm[lane * OUTC + j]) + a1 * __ldg(&Wm[(lane + 32) * OUTC + j]);
        #pragma unroll
        for (int off = 16; off > 0; off >>= 1)
            p += __shfl_down_sync(0xFFFFFFFFu, p, off);
        if (lane == 0)
            out_prob[(long long)warp * OUTC + j] = 1.0f / (1.0f + expf(-(p + __ldg(&bm[j]))));
    }
}

// ---------------- launch ----------------
extern "C" void kernel_launch(void* const* d_in, const int* in_sizes, int n_in,
                              void* d_out, int out_size)
{
    const float* x   = (const float*)d_in[0];
    const void*  ei  = d_in[1];
    const void*  idx = d_in[2];
    const float* W0  = (const float*)d_in[3];
    const float* b0  = (const float*)d_in[4];
    const float* W1  = (const float*)d_in[5];
    const float* b1  = (const float*)d_in[6];
    const float* Wm  = (const float*)d_in[7];
    const float* bm  = (const float*)d_in[8];

    int n = in_sizes[0] / INC;
    if (n > MAXN) n = MAXN;
    int e32 = in_sizes[1] / 2;                    // edge count if indices are int32
    int nsel = out_size / (HID + OUTC);           // robust to idx dtype packing

    float* out_hsel = (float*)d_out;
    float* out_prob = (float*)d_out + (size_t)nsel * HID;

    detect_kernel<<<1, 512>>>((const unsigned int*)ei);

    init_deg_kernel<<<(n + 255) / 256, 256>>>(n);
    count_deg_kernel<<<(e32 + 255) / 256, 256>>>(ei, e32);
    dinv_kernel<<<(n + 255) / 256, 256>>>(n);

    int gblocks = (n + 63) / 64;
    long long sthreads = (long long)e32 * 16;
    int sblocks = (int)((sthreads + 255) / 256);

    gemm_kernel<INC, 1><<<gblocks, 256>>>(x, W0, nullptr, n);
    scatter_kernel<1><<<sblocks, 256>>>(ei, e32);

    gemm_kernel<HID, 2><<<gblocks, 256>>>(nullptr, W1, b0, n);
    scatter_kernel<2><<<sblocks, 256>>>(ei, e32);

    final_kernel<<<(nsel * 32 + 255) / 256, 256>>>(idx, nsel, b1, Wm, bm,
                                                   out_hsel, out_prob);
}

// round 3
// speedup vs baseline: 1.3753x; 1.3753x over previous
#include <cuda_runtime.h>
#include <math.h>

#define NEG_SLOPE 0.01f
#define MAXN 100000
#define EMAX 3200000
#define NB_MAX 128
#define HID 64
#define INC 128
#define OUTC 5

// ---------------- scratch (device globals; no allocation allowed) ----------------
__device__ int   g_w8;                        // 1 if indices are int64, 0 if int32
__device__ int   g_cnt [MAXN];                // in-degree counts
__device__ int   g_bsum[NB_MAX];              // block sums for scan
__device__ int   g_off [MAXN + 1];            // CSR row offsets
__device__ int   g_pos [MAXN];                // fill cursors
__device__ int   g_srcs[EMAX];                // src ids sorted by dst
__device__ float g_dinv[MAXN];
__device__ __align__(256) float g_h   [(size_t)MAXN * HID];
__device__ __align__(256) float g_agg [(size_t)MAXN * HID];
__device__ __align__(256) float g_h1  [(size_t)MAXN * HID];
__device__ __align__(256) float g_agg1[(size_t)MAXN * HID];

// ---------------- helpers ----------------
__device__ __forceinline__ int ldidx(const void* p, long long i, int w8) {
    return w8 ? (int)__ldg((const long long*)p + i) : __ldg((const int*)p + i);
}
__device__ __forceinline__ float leaky(float v) { return v > 0.f ? v : NEG_SLOPE * v; }

#define FFMA2(d, a, b, c) \
    asm("fma.rn.f32x2 %0, %1, %2, %3;" : "=l"(d) : "l"(a), "l"(b), "l"(c))
#define MULX2(d, a, b) \
    asm("mul.rn.f32x2 %0, %1, %2;" : "=l"(d) : "l"(a), "l"(b))
#define PACK2(d, lo, hi) \
    asm("mov.b64 %0, {%1, %2};" : "=l"(d) : "f"(lo), "f"(hi))

// ---------------- dtype detection ----------------
__global__ void detect_kernel(const unsigned int* p) {
    __shared__ int nz;
    if (threadIdx.x == 0) nz = 0;
    __syncthreads();
    if (p[2 * threadIdx.x + 1] != 0u) atomicExch(&nz, 1);
    __syncthreads();
    if (threadIdx.x == 0) g_w8 = (nz == 0) ? 1 : 0;
}

// ---------------- CSR build ----------------
__global__ void zero_cnt_kernel(int n) {
    int i = blockIdx.x * blockDim.x + threadIdx.x;
    if (i < n) g_cnt[i] = 0;
}

__global__ void count_kernel(const void* ei, int e32) {
    int w8 = g_w8;
    long long E = w8 ? (e32 >> 1) : e32;
    long long e = (long long)blockIdx.x * blockDim.x + threadIdx.x;
    if (e >= E) return;
    int d = ldidx(ei, E + e, w8);
    atomicAdd(&g_cnt[d], 1);
}

__global__ void dinv_kernel(int n) {
    int i = blockIdx.x * blockDim.x + threadIdx.x;
    if (i < n) g_dinv[i] = rsqrtf((float)g_cnt[i] + 1.0f);   // +1 self loop
}

__global__ void scanA_kernel(int n) {           // grid nb, block 1024
    __shared__ int sh[1024];
    int i = blockIdx.x * 1024 + threadIdx.x;
    sh[threadIdx.x] = (i < n) ? g_cnt[i] : 0;
    __syncthreads();
    for (int s = 512; s > 0; s >>= 1) {
        if (threadIdx.x < s) sh[threadIdx.x] += sh[threadIdx.x + s];
        __syncthreads();
    }
    if (threadIdx.x == 0) g_bsum[blockIdx.x] = sh[0];
}

__global__ void scanB_kernel(int nb) {          // 1 block, NB_MAX threads
    __shared__ int sh[NB_MAX];
    int t = threadIdx.x;
    int v0 = (t < nb) ? g_bsum[t] : 0;
    sh[t] = v0;
    __syncthreads();
    for (int o = 1; o < NB_MAX; o <<= 1) {
        int u = (t >= o) ? sh[t - o] : 0;
        __syncthreads();
        sh[t] += u;
        __syncthreads();
    }
    if (t < nb) g_bsum[t] = sh[t] - v0;         // exclusive
}

__global__ void scanC_kernel(int n) {           // grid nb, block 1024
    __shared__ int sh[1024];
    int b = blockIdx.x, t = threadIdx.x;
    int i = b * 1024 + t;
    int v = (i < n) ? g_cnt[i] : 0;
    sh[t] = v;
    __syncthreads();
    for (int o = 1; o < 1024; o <<= 1) {
        int u = (t >= o) ? sh[t - o] : 0;
        __syncthreads();
        sh[t] += u;
        __syncthreads();
    }
    int base = g_bsum[b];
    if (i < n) {
        int off = base + sh[t] - v;             // exclusive
        g_off[i] = off;
        g_pos[i] = off;
        if (i == n - 1) g_off[n] = base + sh[t];
    }
}

__global__ void fill_kernel(const void* ei, int e32) {
    int w8 = g_w8;
    long long E = w8 ? (e32 >> 1) : e32;
    long long e = (long long)blockIdx.x * blockDim.x + threadIdx.x;
    if (e >= E) return;
    int s = ldidx(ei, e, w8);
    int d = ldidx(ei, E + e, w8);
    int p = atomicAdd(&g_pos[d], 1);
    if (p < EMAX) g_srcs[p] = s;
}

// ---------------- fused GEMM (f32x2 packed FMA) ----------------
// LAYER==1: H = X @ W0            -> g_h
// LAYER==2: A = leaky(g_agg + b0) ; H = A @ W1 -> g_h1
template<int K, int LAYER>
__global__ void gemm_kernel(const float* __restrict__ Xext,
                            const float* __restrict__ W,
                            const float* __restrict__ bias,
                            int n)
{
    const int CK = 32;
    __shared__ __align__(16) float Xs2[64][2 * CK];   // duplicated pairs (v,v)
    __shared__ __align__(16) float Ws[CK][64];

    int tid = threadIdx.x;
    int tx = tid & 15;          // 16 col-groups of 4
    int ty = tid >> 4;          // 16 row-groups of 4
    int rb = blockIdx.x * 64;

    unsigned long long acc[4][2] = {};   // zero bits == (0.f, 0.f)

    for (int kc = 0; kc < K; kc += CK) {
        for (int i = tid; i < 64 * CK; i += 256) {
            int r = i >> 5, c = i & 31;
            int row = rb + r;
            float v = 0.f;
            if (row < n) {
                if (LAYER == 1) {
                    v = Xext[(long long)row * K + kc + c];
                } else {
                    v = leaky(g_agg[(long long)row * K + kc + c] + bias[kc + c]);
                }
            }
            float2 vv = make_float2(v, v);
            *(float2*)&Xs2[r][2 * c] = vv;
        }
        for (int i = tid; i < CK * 64; i += 256) {
            int k = i >> 6, c = i & 63;
            Ws[k][c] = W[(long long)(kc + k) * 64 + c];
        }
        __syncthreads();

        #pragma unroll
        for (int kk = 0; kk < CK; kk++) {
            ulonglong2 wv = *(const ulonglong2*)&Ws[kk][tx * 4];
            #pragma unroll
            for (int i = 0; i < 4; i++) {
                unsigned long long xx =
                    *(const unsigned long long*)&Xs2[ty * 4 + i][2 * kk];
                FFMA2(acc[i][0], xx, wv.x, acc[i][0]);
                FFMA2(acc[i][1], xx, wv.y, acc[i][1]);
            }
        }
        __syncthreads();
    }

    float* H = (LAYER == 1) ? g_h : g_h1;
    #pragma unroll
    for (int i = 0; i < 4; i++) {
        int row = rb + ty * 4 + i;
        if (row >= n) break;
        ulonglong2 hv;
        hv.x = acc[i][0];
        hv.y = acc[i][1];
        *(ulonglong2*)&H[(long long)row * 64 + tx * 4] = hv;
    }
}

// ---------------- CSR pull aggregation ----------------
// AGG[d] = dinv[d]^2 * H[d] + sum_{s in N(d)} dinv[s]*dinv[d] * H[s]
template<int LAYER>
__global__ void agg_kernel(int n)
{
    int gid = blockIdx.x * blockDim.x + threadIdx.x;
    int row = gid >> 4;
    int t = gid & 15;
    if (row >= n) return;

    const float* H = (LAYER == 1) ? g_h : g_h1;
    float*     AGG = (LAYER == 1) ? g_agg : g_agg1;

    float dd = g_dinv[row];
    float d2 = dd * dd;
    float4 hv = *(const float4*)(H + (long long)row * 64 + t * 4);
    float4 acc = make_float4(hv.x * d2, hv.y * d2, hv.z * d2, hv.w * d2);

    int beg = g_off[row], end = g_off[row + 1];
    for (int e = beg; e < end; e++) {
        int s = g_srcs[e];
        float c = __ldg(&g_dinv[s]) * dd;
        float4 sv = *(const float4*)(H + (long long)s * 64 + t * 4);
        acc.x += c * sv.x;
        acc.y += c * sv.y;
        acc.z += c * sv.z;
        acc.w += c * sv.w;
    }
    *(float4*)(AGG + (long long)row * 64 + t * 4) = acc;
}

// ---------------- final: select rows, activation, tiny MLP + sigmoid ----------------
__global__ void final_kernel(const void* idxp, int nsel,
                             const float* __restrict__ b1,
                             const float* __restrict__ Wm,
                             const float* __restrict__ bm,
                             float* __restrict__ out_hsel,
                             float* __restrict__ out_prob)
{
    int w8 = g_w8;
    int warp = (blockIdx.x * blockDim.x + threadIdx.x) >> 5;
    int lane = threadIdx.x & 31;
    if (warp >= nsel) return;

    int v = ldidx(idxp, warp, w8);
    float a0 = leaky(g_agg1[(long long)v * 64 + lane]      + __ldg(&b1[lane]));
    float a1 = leaky(g_agg1[(long long)v * 64 + lane + 32] + __ldg(&b1[lane + 32]));
    out_hsel[(long long)warp * 64 + lane]      = a0;
    out_hsel[(long long)warp * 64 + lane + 32] = a1;

    #pragma unroll
    for (int j = 0; j < OUTC; j++) {
        float p = a0 * __ldg(&Wm[lane * OUTC + j]) + a1 * __ldg(&Wm[(lane + 32) * OUTC + j]);
        #pragma unroll
        for (int off = 16; off > 0; off >>= 1)
            p += __shfl_down_sync(0xFFFFFFFFu, p, off);
        if (lane == 0)
            out_prob[(long long)warp * OUTC + j] = 1.0f / (1.0f + expf(-(p + __ldg(&bm[j]))));
    }
}

// ---------------- launch ----------------
extern "C" void kernel_launch(void* const* d_in, const int* in_sizes, int n_in,
                              void* d_out, int out_size)
{
    const float* x   = (const float*)d_in[0];
    const void*  ei  = d_in[1];
    const void*  idx = d_in[2];
    const float* W0  = (const float*)d_in[3];
    const float* b0  = (const float*)d_in[4];
    const float* W1  = (const float*)d_in[5];
    const float* b1  = (const float*)d_in[6];
    const float* Wm  = (const float*)d_in[7];
    const float* bm  = (const float*)d_in[8];

    int n = in_sizes[0] / INC;
    if (n > MAXN) n = MAXN;
    int e32 = in_sizes[1] / 2;                  // edge count if int32
    int nsel = out_size / (HID + OUTC);

    float* out_hsel = (float*)d_out;
    float* out_prob = (float*)d_out + (size_t)nsel * HID;

    int nb = (n + 1023) / 1024;                 // <= NB_MAX for n<=100k

    detect_kernel<<<1, 512>>>((const unsigned int*)ei);

    zero_cnt_kernel<<<(n + 255) / 256, 256>>>(n);
    count_kernel<<<(e32 + 255) / 256, 256>>>(ei, e32);
    dinv_kernel<<<(n + 255) / 256, 256>>>(n);

    scanA_kernel<<<nb, 1024>>>(n);
    scanB_kernel<<<1, NB_MAX>>>(nb);
    scanC_kernel<<<nb, 1024>>>(n);
    fill_kernel<<<(e32 + 255) / 256, 256>>>(ei, e32);

    int gblocks = (n + 63) / 64;
    int ablocks = (int)(((long long)n * 16 + 255) / 256);

    gemm_kernel<INC, 1><<<gblocks, 256>>>(x, W0, nullptr, n);
    agg_kernel<1><<<ablocks, 256>>>(n);

    gemm_kernel<HID, 2><<<gblocks, 256>>>(nullptr, W1, b0, n);
    agg_kernel<2><<<ablocks, 256>>>(n);

    final_kernel<<<(nsel * 32 + 255) / 256, 256>>>(idx, nsel, b1, Wm, bm,
                                                   out_hsel, out_prob);
}